// round 17
// baseline (speedup 1.0000x reference)
#include <cuda_runtime.h>
#include <cuda_fp16.h>
#include <math.h>
#include <stdint.h>

#define Qn 4096
#define Nn 65536
#define Dn 32
#define DK 48               // 32 data dims + 16-dim aug block (biases folded into GEMM)
#define BM 128
#define BN 128
#define SPLITN 9
#define NT2 512
#define LOG2E 1.4426950408889634f
#define XSTR 112            // X smem row stride (48 halves + pad)
#define TILE_X (128 * XSTR)
#define YROW 64             // Y gmem row: 64 halves = 128B (fragment-permuted, padded)
#define YSTR 144            // Y smem row stride (128B payload + 16B pad; conflict-free)
#define TILE_Y (128 * YSTR) // 18432

// ---------------- device scratch ----------------
__device__ __align__(16) __half g_Xh[Qn * DK];    // [0:32)=fp16(L*x), [32]=bx_h,[33]=bx_l,[34]=1,[35]=1
__device__ __align__(16) __half g_Yh[Nn * YROW];  // fragment-permuted rows (see prep_y48)
__device__ float g_partial[SPLITN * Qn];
__device__ float g_wpart[Nn / 256];

// ---------------- smem layout (bytes) ----------------
#define SM_XH 0                       // 14336
#define SM_Y  TILE_X                  // 4 bufs * 18432 = 73728
#define SM_BYTES (TILE_X + 4 * TILE_Y)  // 88064

__device__ __forceinline__ uint32_t smem_u32(const void* p) {
    uint32_t a;
    asm("{ .reg .u64 t; cvta.to.shared.u64 t, %1; cvt.u32.u64 %0, t; }" : "=r"(a) : "l"(p));
    return a;
}

#define MMA(d, a, b0, b1) \
    asm volatile("mma.sync.aligned.m16n8k16.row.col.f32.f16.f16.f32 " \
        "{%0,%1,%2,%3}, {%4,%5,%6,%7}, {%8,%9}, {%0,%1,%2,%3};" \
        : "+f"((d)[0]), "+f"((d)[1]), "+f"((d)[2]), "+f"((d)[3]) \
        : "r"((a)[0]), "r"((a)[1]), "r"((a)[2]), "r"((a)[3]), "r"(b0), "r"(b1))

#define CPA16(dst, src) \
    asm volatile("cp.async.cg.shared.global [%0], [%1], 16;" :: "r"(dst), "l"(src) : "memory")

// FFMA-pipe exp2: magic-number range reduction + deg-5 Horner + exponent splice.
// Valid for x <= ~127; clamped below -126 (result ~1e-38, negligible in the sum).
__device__ __forceinline__ float fexp2(float x) {
    x = fmaxf(x, -126.0f);
    float t = __fadd_rn(x, 12582912.0f);                  // n = round(x) in low mantissa
    float f = __fadd_rn(x, -__fadd_rn(t, -12582912.0f));  // f in [-0.5, 0.5]
    float p = fmaf(f, 0.0013333558f, 0.0096181291f);
    p = fmaf(f, p, 0.0555041087f);
    p = fmaf(f, p, 0.2402265070f);
    p = fmaf(f, p, 0.6931471806f);
    p = fmaf(f, p, 1.0f);
    return __int_as_float(__float_as_int(p) + (__float_as_int(t) << 23));
}

// ---------------- prep ----------------
__global__ void prep_x48(const float* __restrict__ X) {
    int i = blockIdx.x * blockDim.x + threadIdx.x;
    if (i >= Qn) return;
    __half h[DK];
    float qn = 0.f;
#pragma unroll
    for (int d = 0; d < Dn; d++) {
        float x = X[i * Dn + d];
        qn += x * x;
        h[d] = __float2half_rn(x * LOG2E);
    }
    float bxv = -0.5f * LOG2E * qn;
    __half bh = __float2half_rn(bxv);
    __half bl = __float2half_rn(bxv - __half2float(bh));
    h[32] = bh; h[33] = bl;
    h[34] = __float2half_rn(1.0f); h[35] = __float2half_rn(1.0f);
#pragma unroll
    for (int d = 36; d < DK; d++) h[d] = __float2half_rn(0.f);
#pragma unroll
    for (int c = 0; c < 6; c++)
        *(uint4*)(g_Xh + i * DK + c * 8) = *(const uint4*)(h + c * 8);
}

// Builds fragment-permuted Y rows: for lane-group g (= lane&3), 32-byte chunk at
// byte g*32 holds [kk0b0, kk0b1, kk1b0, kk1b1] (16B, one LDS.128) then
// [aug b0, aug b1] (8B, one LDS.64) then 8B pad.
// Old u32 index within the 24-u32 logical row: kkXbY -> g + kk*8 + Y*4; aug bY -> 16+g+Y*4.
__global__ void prep_y48(const float* __restrict__ Y, const float* __restrict__ W) {
    __shared__ float red[256];
    int j = blockIdx.x * blockDim.x + threadIdx.x;
    __half h[DK];
    float kn = 0.f;
#pragma unroll
    for (int d = 0; d < Dn; d++) {
        float y = Y[j * Dn + d];
        kn += y * y;
        h[d] = __float2half_rn(y);
    }
    float w = W[j];
    float byv = LOG2E * (-0.5f * kn + __logf(w));
    __half bh = __float2half_rn(byv);
    __half bl = __float2half_rn(byv - __half2float(bh));
    h[32] = __float2half_rn(1.0f); h[33] = __float2half_rn(1.0f);
    h[34] = bh; h[35] = bl;
#pragma unroll
    for (int d = 36; d < DK; d++) h[d] = __float2half_rn(0.f);

    const uint32_t* hu = (const uint32_t*)h;
    uint32_t p[32];
#pragma unroll
    for (int g = 0; g < 4; g++) {
        p[g * 8 + 0] = hu[g];
        p[g * 8 + 1] = hu[g + 4];
        p[g * 8 + 2] = hu[g + 8];
        p[g * 8 + 3] = hu[g + 12];
        p[g * 8 + 4] = hu[16 + g];
        p[g * 8 + 5] = hu[20 + g];
        p[g * 8 + 6] = 0;
        p[g * 8 + 7] = 0;
    }
#pragma unroll
    for (int c = 0; c < 8; c++)
        *(uint4*)(g_Yh + j * YROW + c * 8) = ((const uint4*)p)[c];

    red[threadIdx.x] = w;
    __syncthreads();
    for (int k = 128; k > 0; k >>= 1) {
        if (threadIdx.x < k) red[threadIdx.x] += red[threadIdx.x + k];
        __syncthreads();
    }
    if (threadIdx.x == 0) g_wpart[blockIdx.x] = red[0];
}

// ---------------- main ----------------
__device__ __forceinline__ void prefetch_tile(uint32_t sb, int buf, int jb, int tid) {
    // 128 rows * 8 chunks of 16B = 1024 chunks, 4 per thread (power-of-2 indexing)
    uint32_t base = sb + SM_Y + buf * TILE_Y;
#pragma unroll
    for (int c = 0; c < 4; c++) {
        int id = tid + 256 * c;
        int row = id >> 3, col = id & 7;
        CPA16(base + row * YSTR + col * 16, g_Yh + (jb + row) * YROW + col * 8);
    }
}

__global__ __launch_bounds__(256, 2) void kde_main() {
    extern __shared__ __align__(128) char smem[];
    const uint32_t sb = smem_u32(smem);
    const int tid = threadIdx.x, lane = tid & 31, wid = tid >> 5;
    const int wm = wid >> 1, wn = wid & 1;    // 4 warps M-dir, 2 warps N-dir
    const int qrow = lane >> 2;               // PTX groupID
    const int kb = (lane & 3) * 4;            // k-pair byte offset (A side)
    const int gb = (lane & 3) * 32;           // fragment-chunk byte offset (Y side)
    const int qb = blockIdx.x * BM;
    const int split = blockIdx.y;

    // prologue: 2 tiles in flight before touching X
    prefetch_tile(sb, 0, split * BN, tid);
    asm volatile("cp.async.commit_group;" ::: "memory");
    prefetch_tile(sb, 1, (split + SPLITN) * BN, tid);
    asm volatile("cp.async.commit_group;" ::: "memory");

    // load X tile into padded smem (128 rows * 6 chunks, 3 per thread)
#pragma unroll
    for (int c = 0; c < 3; c++) {
        int id = tid + 256 * c;
        int row = id / 6, col = id % 6;
        *(uint4*)(smem + SM_XH + row * XSTR + col * 16) =
            *(const uint4*)(g_Xh + (qb + row) * DK + col * 8);
    }
    __syncthreads();

    // hoist A fragments (validated m16n8k16 A table):
    //   a0=(r,k) a1=(r+8,k) a2=(r,k+8) a3=(r+8,k+8)
    uint32_t ah[2][2][4], aga[2][4];
#pragma unroll
    for (int mt = 0; mt < 2; mt++) {
        int row = wm * 32 + mt * 16 + qrow;
#pragma unroll
        for (int kk = 0; kk < 2; kk++) {
            const char* ph = smem + SM_XH + row * XSTR + kk * 32 + kb;
            ah[mt][kk][0] = *(const uint32_t*)(ph);
            ah[mt][kk][1] = *(const uint32_t*)(ph + 8 * XSTR);
            ah[mt][kk][2] = *(const uint32_t*)(ph + 16);
            ah[mt][kk][3] = *(const uint32_t*)(ph + 8 * XSTR + 16);
        }
        const char* pa = smem + SM_XH + row * XSTR + 64 + kb;   // aug block k=32..47
        aga[mt][0] = *(const uint32_t*)(pa);
        aga[mt][1] = *(const uint32_t*)(pa + 8 * XSTR);
        aga[mt][2] = *(const uint32_t*)(pa + 16);
        aga[mt][3] = *(const uint32_t*)(pa + 8 * XSTR + 16);
    }

    float rs[4] = {0.f, 0.f, 0.f, 0.f};
    int idx = 0;
    for (int t = split; t < NT2; t += SPLITN, idx++) {
        const int buf = idx & 3;
        const int tn2 = t + 2 * SPLITN;
        if (tn2 < NT2)
            prefetch_tile(sb, (idx + 2) & 3, tn2 * BN, tid);
        asm volatile("cp.async.commit_group;" ::: "memory");   // possibly empty group
        asm volatile("cp.async.wait_group 2;" ::: "memory");   // tile idx resident
        __syncthreads();

        const char* yb = smem + SM_Y + buf * TILE_Y;

#pragma unroll
        for (int g = 0; g < 4; g++) {
            // B fragments from fragment-permuted rows: LDS.128 + LDS.64 per nt
            uint32_t bh[2][2][2], bga[2][2];   // [kk][nt][reg]
#pragma unroll
            for (int nt = 0; nt < 2; nt++) {
                int nrow = wn * 64 + g * 16 + nt * 8 + qrow;
                const char* pb = yb + nrow * YSTR + gb;
                uint4 v = *(const uint4*)(pb);
                bh[0][nt][0] = v.x; bh[0][nt][1] = v.y;
                bh[1][nt][0] = v.z; bh[1][nt][1] = v.w;
                uint2 va = *(const uint2*)(pb + 16);
                bga[nt][0] = va.x; bga[nt][1] = va.y;
            }

            float acc[2][2][4];
#pragma unroll
            for (int mt = 0; mt < 2; mt++)
#pragma unroll
                for (int nt = 0; nt < 2; nt++)
#pragma unroll
                    for (int q = 0; q < 4; q++) acc[mt][nt][q] = 0.f;

#pragma unroll
            for (int kk = 0; kk < 2; kk++)
#pragma unroll
                for (int mt = 0; mt < 2; mt++)
#pragma unroll
                    for (int nt = 0; nt < 2; nt++)
                        MMA(acc[mt][nt], ah[mt][kk], bh[kk][nt][0], bh[kk][nt][1]);
#pragma unroll
            for (int mt = 0; mt < 2; mt++)
#pragma unroll
                for (int nt = 0; nt < 2; nt++)
                    MMA(acc[mt][nt], aga[mt], bga[nt][0], bga[nt][1]);

            // epilogue: hybrid exp2, row-aligned —
            //   acc[0],acc[1] belong to row qrow      -> rs[mt*2+0]
            //   acc[2],acc[3] belong to row qrow + 8  -> rs[mt*2+1]
            // pipe split WITHIN each row pair: MUFU for [0]/[2], FFMA poly for [1]/[3]
#pragma unroll
            for (int mt = 0; mt < 2; mt++)
#pragma unroll
                for (int nt = 0; nt < 2; nt++) {
                    float e0, e2;
                    asm("ex2.approx.f32 %0, %1;" : "=f"(e0) : "f"(acc[mt][nt][0]));
                    float e1 = fexp2(acc[mt][nt][1]);
                    asm("ex2.approx.f32 %0, %1;" : "=f"(e2) : "f"(acc[mt][nt][2]));
                    float e3 = fexp2(acc[mt][nt][3]);
                    rs[mt * 2 + 0] += e0 + e1;
                    rs[mt * 2 + 1] += e2 + e3;
                }
        }
    }

    // deterministic reduction: 4 lanes share each row
#pragma unroll
    for (int k = 0; k < 4; k++) {
        rs[k] += __shfl_xor_sync(0xffffffffu, rs[k], 1);
        rs[k] += __shfl_xor_sync(0xffffffffu, rs[k], 2);
    }
    __syncthreads();
    float* red = (float*)(smem + SM_Y);  // 256 floats, buffers no longer needed
    if ((lane & 3) == 0) {
#pragma unroll
        for (int k = 0; k < 4; k++) {
            int mt = k >> 1, hf = k & 1;
            int row = wm * 32 + mt * 16 + (lane >> 2) + hf * 8;
            red[wn * 128 + row] = rs[k];
        }
    }
    __syncthreads();
    if (tid < 128)
        g_partial[split * Qn + qb + tid] = red[tid] + red[128 + tid];
}

__global__ void finalize(float* __restrict__ out) {
    __shared__ float red[256];
    int tid = threadIdx.x;
    red[tid] = g_wpart[tid];           // 256 per-block w partials
    __syncthreads();
    for (int k = 128; k > 0; k >>= 1) {
        if (tid < k) red[tid] += red[tid + k];
        __syncthreads();
    }
    float lsw = logf(red[0]);
    int i = blockIdx.x * blockDim.x + tid;
    float s = 0.f;
#pragma unroll
    for (int k = 0; k < SPLITN; k++) s += g_partial[k * Qn + i];
    out[i] = logf(s) - 29.40603306f - lsw;
}

// ---------------------------------------------------------------------------
extern "C" void kernel_launch(void* const* d_in, const int* in_sizes, int n_in,
                              void* d_out, int out_size) {
    const float* X = (const float*)d_in[0];  // [4096,32]
    const float* Y = (const float*)d_in[1];  // [65536,32]
    const float* W = (const float*)d_in[2];  // [65536]
    float* out = (float*)d_out;

    cudaFuncSetAttribute(kde_main, cudaFuncAttributeMaxDynamicSharedMemorySize, SM_BYTES);

    prep_x48<<<(Qn + 255) / 256, 256>>>(X);
    prep_y48<<<Nn / 256, 256>>>(Y, W);
    dim3 grid(Qn / BM, SPLITN);
    kde_main<<<grid, 256, SM_BYTES>>>();
    finalize<<<Qn / 256, 256>>>(out);
}